// round 1
// baseline (speedup 1.0000x reference)
#include <cuda_runtime.h>
#include <math.h>
#include <stdint.h>

#define BB 128
#define LL 100
#define HID 256
#define IND 160
#define NCAP 1600      // LL * 16 capsules per example
#define CAPD 16
#define NCLS 19
#define ODIM 304       // NCLS * CAPD

// ---------------- device scratch (static, no allocs) ----------------
__device__ float g_emb [BB*LL*IND];          // 8.2 MB
__device__ float g_xgf [BB*LL*1024];         // 52 MB
__device__ float g_xgb [BB*LL*1024];         // 52 MB
__device__ float g_hbuf[2*2*BB*HID];         // double-buffered h, both dirs
__device__ float g_xf  [BB*LL*HID];
__device__ float g_xb  [BB*LL*HID];
__device__ float g_x   [BB*LL*HID];
__device__ float g_att [BB*LL];
__device__ float g_u   [BB*NCAP*CAPD];
__device__ float g_uhat[(size_t)BB*NCAP*ODIM]; // 249 MB
__device__ float g_bb  [(size_t)BB*NCAP*NCLS]; // 15.6 MB
__device__ float g_s   [BB*ODIM];
__device__ float g_v   [BB*ODIM];
__device__ unsigned long long g_bar = 0;       // monotone barrier counter

// ---------------- grid barrier (graph-safe, monotone) ----------------
__device__ __forceinline__ void grid_barrier(unsigned nb) {
    __threadfence();
    __syncthreads();
    if (threadIdx.x == 0) {
        unsigned long long my = atomicAdd(&g_bar, 1ULL) + 1ULL;
        unsigned long long target = ((my + nb - 1ULL) / nb) * nb;
        while (*((volatile unsigned long long*)&g_bar) < target) { }
        __threadfence();
    }
    __syncthreads();
}

// ---------------- K1: embedding gather ----------------
__global__ void embed_kernel(const int* __restrict__ word, const int* __restrict__ tag,
                             const int* __restrict__ p1,   const int* __restrict__ p2,
                             const float* __restrict__ we, const float* __restrict__ te,
                             const float* __restrict__ p1e,const float* __restrict__ p2e) {
    int idx = blockIdx.x * blockDim.x + threadIdx.x;
    if (idx >= BB*LL*IND) return;
    int bl = idx / IND;
    int d  = idx - bl * IND;
    float v;
    if (d < 100)      v = we[(size_t)word[bl]*100 + d];
    else if (d < 120) v = te[tag[bl]*20 + (d-100)];
    else if (d < 140) v = p1e[p1[bl]*20 + (d-120)];
    else              v = p2e[p2[bl]*20 + (d-140)];
    g_emb[idx] = v;
}

// ---------------- K2: xg = emb @ w_ih^T + b_ih + b_hh (both dirs) ----------------
// C[M=12800, N=1024], K=160. 64x64 tile, 16x16 threads, 4x4 micro-tile.
__global__ void __launch_bounds__(256) gemm_xg_kernel(
        const float* __restrict__ wf, const float* __restrict__ wbk,
        const float* __restrict__ bif, const float* __restrict__ bhf,
        const float* __restrict__ bib, const float* __restrict__ bhb) {
    __shared__ float As[16][64];
    __shared__ float Ws[16][64];
    int dir = blockIdx.z;
    const float* W  = dir ? wbk : wf;
    const float* bi = dir ? bib : bif;
    const float* bh = dir ? bhb : bhf;
    float* C = dir ? g_xgb : g_xgf;
    int n0 = blockIdx.x * 64;
    int m0 = blockIdx.y * 64;
    int tid = threadIdx.x;
    int tx = tid & 15, ty = tid >> 4;
    int lrow = tid >> 2, lq = tid & 3;
    float acc[4][4] = {};
    for (int k0 = 0; k0 < 160; k0 += 16) {
        float4 av = *(const float4*)(g_emb + (size_t)(m0 + lrow) * 160 + k0 + lq * 4);
        float4 wv = *(const float4*)(W     + (size_t)(n0 + lrow) * 160 + k0 + lq * 4);
        As[lq*4+0][lrow] = av.x; As[lq*4+1][lrow] = av.y;
        As[lq*4+2][lrow] = av.z; As[lq*4+3][lrow] = av.w;
        Ws[lq*4+0][lrow] = wv.x; Ws[lq*4+1][lrow] = wv.y;
        Ws[lq*4+2][lrow] = wv.z; Ws[lq*4+3][lrow] = wv.w;
        __syncthreads();
        #pragma unroll
        for (int kk = 0; kk < 16; ++kk) {
            float a[4], w[4];
            #pragma unroll
            for (int e = 0; e < 4; ++e) { a[e] = As[kk][ty*4+e]; w[e] = Ws[kk][tx*4+e]; }
            #pragma unroll
            for (int i = 0; i < 4; ++i)
                #pragma unroll
                for (int j = 0; j < 4; ++j)
                    acc[i][j] += a[i] * w[j];
        }
        __syncthreads();
    }
    #pragma unroll
    for (int i = 0; i < 4; ++i) {
        int m = m0 + ty*4 + i;
        #pragma unroll
        for (int j = 0; j < 4; ++j) {
            int n = n0 + tx*4 + j;
            C[(size_t)m * 1024 + n] = acc[i][j] + bi[n] + bh[n];
        }
    }
}

// ---------------- K3: persistent BiLSTM ----------------
// 256 blocks = 2 dirs x (8 b-tiles of 16) x (16 u-tiles of 16). Thread owns one (b,u).
// w_hh slice (64 rows x 256) cached in smem for all 100 steps.
#define WS_STRIDE 260
#define LSTM_SMEM ((4*16*WS_STRIDE + 16*256) * 4)

__global__ void __launch_bounds__(256, 2) lstm_kernel(
        const float* __restrict__ whh_f, const float* __restrict__ whh_b) {
    extern __shared__ float sm[];
    float* w_s = sm;                       // [4][16][WS_STRIDE]
    float* h_s = sm + 4*16*WS_STRIDE;      // [16][256]
    int blk = blockIdx.x;
    int dir = blk >> 7;
    int rem = blk & 127;
    int bt = rem >> 4;     // 0..7
    int ut = rem & 15;     // 0..15
    int b0 = bt * 16;
    int u0 = ut * 16;
    int tid = threadIdx.x;
    int b_local = tid >> 4;
    int u_local = tid & 15;
    int b = b0 + b_local;
    int u = u0 + u_local;
    const float* whh = dir ? whh_b : whh_f;
    const float* xg  = dir ? g_xgb : g_xgf;
    float* xout      = dir ? g_xb  : g_xf;

    // cache w_hh rows: g*256 + u0 + ul for g in 0..3, ul in 0..15
    for (int x = tid; x < 64*64; x += 256) {
        int row = x >> 6;       // 0..63
        int q   = x & 63;       // float4 index within 256
        int g = row >> 4, ul = row & 15;
        int R = g*256 + u0 + ul;
        float4 v = *(const float4*)(whh + (size_t)R*256 + q*4);
        *(float4*)(w_s + (g*16+ul)*WS_STRIDE + q*4) = v;
    }
    float c_reg = 0.f;
    g_hbuf[((0*2 + dir)*BB + b)*HID + u] = 0.f;
    grid_barrier(gridDim.x);

    int cur = 0;
    for (int step = 0; step < LL; ++step) {
        int t = dir ? (LL-1-step) : step;
        // stage h_prev tile (16 b x 256) into smem, L2-coherent loads
        const float4* hsrc = (const float4*)(g_hbuf + ((size_t)(cur*2 + dir)*BB + b0)*HID);
        for (int q = tid; q < 16*64; q += 256) {
            float4 v = __ldcg(hsrc + q);
            *(float4*)(h_s + q*4) = v;
        }
        __syncthreads();

        const float* xgp = xg + ((size_t)(b*LL + t))*1024 + u;
        float acc0 = xgp[0], acc1 = xgp[256], acc2 = xgp[512], acc3 = xgp[768];
        const float4* hv = (const float4*)(h_s + b_local*256);
        const float4* w0 = (const float4*)(w_s + (0*16 + u_local)*WS_STRIDE);
        const float4* w1 = (const float4*)(w_s + (1*16 + u_local)*WS_STRIDE);
        const float4* w2 = (const float4*)(w_s + (2*16 + u_local)*WS_STRIDE);
        const float4* w3 = (const float4*)(w_s + (3*16 + u_local)*WS_STRIDE);
        #pragma unroll 8
        for (int k = 0; k < 64; ++k) {
            float4 h4 = hv[k];
            float4 a;
            a = w0[k]; acc0 += h4.x*a.x + h4.y*a.y + h4.z*a.z + h4.w*a.w;
            a = w1[k]; acc1 += h4.x*a.x + h4.y*a.y + h4.z*a.z + h4.w*a.w;
            a = w2[k]; acc2 += h4.x*a.x + h4.y*a.y + h4.z*a.z + h4.w*a.w;
            a = w3[k]; acc3 += h4.x*a.x + h4.y*a.y + h4.z*a.z + h4.w*a.w;
        }
        float ig = 1.f / (1.f + expf(-acc0));
        float fg = 1.f / (1.f + expf(-acc1));
        float gg = tanhf(acc2);
        float og = 1.f / (1.f + expf(-acc3));
        c_reg = fg * c_reg + ig * gg;
        float h = og * tanhf(c_reg);
        g_hbuf[(((cur^1)*2 + dir)*BB + b)*HID + u] = h;
        xout[((size_t)(b*LL + t))*HID + u] = h;
        grid_barrier(gridDim.x);
        cur ^= 1;
    }
}

// ---------------- K4: x = hf + hb ----------------
__global__ void addx_kernel() {
    int idx = blockIdx.x * blockDim.x + threadIdx.x;
    if (idx < BB*LL*HID) g_x[idx] = g_xf[idx] + g_xb[idx];
}

// ---------------- K5: entity gather + attention softmax ----------------
__global__ void entity_att_kernel(const int* __restrict__ pos1, const int* __restrict__ pos2) {
    int b = blockIdx.x;
    int tid = threadIdx.x;     // 128
    __shared__ int e1s, e2s;
    __shared__ float he_s[256];
    __shared__ float lg[100];
    __shared__ float mred, sred;
    if (tid < 100) {
        if (pos1[b*100 + tid] == 68) e1s = tid;
        if (pos2[b*100 + tid] == 68) e2s = tid;
    }
    __syncthreads();
    for (int u = tid; u < 256; u += 128)
        he_s[u] = g_x[(size_t)(b*100 + e1s)*256 + u] + g_x[(size_t)(b*100 + e2s)*256 + u];
    __syncthreads();
    int w = tid >> 5, lane = tid & 31;
    for (int l = w; l < 100; l += 4) {
        float s = 0.f;
        const float* xp = g_x + (size_t)(b*100 + l)*256;
        for (int u = lane; u < 256; u += 32) s += xp[u] * he_s[u];
        #pragma unroll
        for (int off = 16; off; off >>= 1) s += __shfl_xor_sync(0xffffffffu, s, off);
        if (lane == 0) lg[l] = s;
    }
    __syncthreads();
    if (tid == 0) {
        float m = -1e30f;
        for (int l = 0; l < 100; ++l) m = fmaxf(m, lg[l]);
        float ssum = 0.f;
        for (int l = 0; l < 100; ++l) ssum += expf(lg[l] - m);
        mred = m; sred = ssum;
    }
    __syncthreads();
    if (tid < 100) g_att[b*100 + tid] = expf(lg[tid] - mred) / sred;
}

// ---------------- K6: primary capsule squash ----------------
__global__ void usq_kernel() {
    int idx = blockIdx.x * blockDim.x + threadIdx.x;
    if (idx >= BB*NCAP) return;
    const float* xp = g_x + (size_t)idx * 16;
    float4 a0 = *(const float4*)(xp + 0);
    float4 a1 = *(const float4*)(xp + 4);
    float4 a2 = *(const float4*)(xp + 8);
    float4 a3 = *(const float4*)(xp + 12);
    float n2 = a0.x*a0.x + a0.y*a0.y + a0.z*a0.z + a0.w*a0.w
             + a1.x*a1.x + a1.y*a1.y + a1.z*a1.z + a1.w*a1.w
             + a2.x*a2.x + a2.y*a2.y + a2.z*a2.z + a2.w*a2.w
             + a3.x*a3.x + a3.y*a3.y + a3.z*a3.z + a3.w*a3.w;
    float sc = (n2 / (1.f + n2)) * rsqrtf(n2 + 1e-9f);
    float* up = g_u + (size_t)idx * 16;
    a0.x*=sc; a0.y*=sc; a0.z*=sc; a0.w*=sc;
    a1.x*=sc; a1.y*=sc; a1.z*=sc; a1.w*=sc;
    a2.x*=sc; a2.y*=sc; a2.z*=sc; a2.w*=sc;
    a3.x*=sc; a3.y*=sc; a3.z*=sc; a3.w*=sc;
    *(float4*)(up + 0)  = a0; *(float4*)(up + 4)  = a1;
    *(float4*)(up + 8)  = a2; *(float4*)(up + 12) = a3;
}

// ---------------- K7: u_hat[b,i,od] = sum_c u[b,i,c] * W_caps[i,c,od] ----------------
__global__ void __launch_bounds__(256) uhat_kernel(const float* __restrict__ Wc) {
    __shared__ float Wsm[16*304];
    __shared__ float Usm[128*16];
    int i = blockIdx.x;
    int tid = threadIdx.x;
    const float* Wp = Wc + (size_t)i * 16 * 304;
    for (int x = tid; x < 16*304; x += 256) Wsm[x] = Wp[x];
    for (int x = tid; x < 128*16; x += 256) {
        int b = x >> 4, c = x & 15;
        Usm[x] = g_u[(size_t)b*25600 + i*16 + c];
    }
    __syncthreads();
    for (int out = tid; out < 128*304; out += 256) {
        int b = out / 304;
        int od = out - b*304;
        float acc = 0.f;
        #pragma unroll
        for (int c = 0; c < 16; ++c) acc += Usm[b*16 + c] * Wsm[c*304 + od];
        g_uhat[((size_t)b*NCAP + i)*ODIM + od] = acc;
    }
}

// ---------------- K8: fused routing pass ----------------
// bb_new = (first ? b_route : bb) + u_hat . v_prev ; c = softmax_o(bb_new)*alpha ;
// s += c * u_hat.  Grid: 128 b x 8 i-chunks. 320 threads (304 active for od work).
__global__ void __launch_bounds__(320) route_kernel(int first, const float* __restrict__ broute) {
    __shared__ float v_s[304], uh_s[304], sacc[304], c_s[19];
    int b = blockIdx.x >> 3;
    int chunk = blockIdx.x & 7;
    int tid = threadIdx.x;
    if (tid < 304) { v_s[tid] = g_v[b*ODIM + tid]; sacc[tid] = 0.f; }
    __syncthreads();
    int i_end = chunk*200 + 200;
    for (int i = chunk*200; i < i_end; ++i) {
        if (tid < 304) uh_s[tid] = g_uhat[((size_t)b*NCAP + i)*ODIM + tid];
        __syncthreads();
        float p = (tid < 304) ? uh_s[tid] * v_s[tid] : 0.f;
        p += __shfl_xor_sync(0xffffffffu, p, 8);
        p += __shfl_xor_sync(0xffffffffu, p, 4);
        p += __shfl_xor_sync(0xffffffffu, p, 2);
        p += __shfl_xor_sync(0xffffffffu, p, 1);
        if (tid < 304 && (tid & 15) == 0) {
            int o = tid >> 4;
            float bbv = (first ? broute[i*NCLS + o]
                               : g_bb[((size_t)b*NCAP + i)*NCLS + o]) + p;
            g_bb[((size_t)b*NCAP + i)*NCLS + o] = bbv;
            c_s[o] = bbv;
        }
        __syncthreads();
        if (tid < 32) {
            float m = (tid < 19) ? c_s[tid] : -1e30f;
            #pragma unroll
            for (int off = 16; off; off >>= 1) m = fmaxf(m, __shfl_xor_sync(0xffffffffu, m, off));
            float e = (tid < 19) ? expf(c_s[tid] - m) : 0.f;
            float ssum = e;
            #pragma unroll
            for (int off = 16; off; off >>= 1) ssum += __shfl_xor_sync(0xffffffffu, ssum, off);
            if (tid < 19) c_s[tid] = (e / ssum) * g_att[b*100 + (i >> 4)];
        }
        __syncthreads();
        if (tid < 304) sacc[tid] += c_s[tid >> 4] * uh_s[tid];
        __syncthreads();
    }
    if (tid < 304) atomicAdd(&g_s[b*ODIM + tid], sacc[tid]);
}

// ---------------- K9: v = squash(s), optional final lengths ----------------
__global__ void squash_v_kernel(float* __restrict__ out, int last) {
    int idx = blockIdx.x * blockDim.x + threadIdx.x;
    if (idx >= BB*NCLS) return;
    const float* sp = g_s + (size_t)idx * 16;
    float4 a0 = *(const float4*)(sp + 0);
    float4 a1 = *(const float4*)(sp + 4);
    float4 a2 = *(const float4*)(sp + 8);
    float4 a3 = *(const float4*)(sp + 12);
    float n2 = a0.x*a0.x + a0.y*a0.y + a0.z*a0.z + a0.w*a0.w
             + a1.x*a1.x + a1.y*a1.y + a1.z*a1.z + a1.w*a1.w
             + a2.x*a2.x + a2.y*a2.y + a2.z*a2.z + a2.w*a2.w
             + a3.x*a3.x + a3.y*a3.y + a3.z*a3.z + a3.w*a3.w;
    float sc = (n2 / (1.f + n2)) * rsqrtf(n2 + 1e-9f);
    float* vp = g_v + (size_t)idx * 16;
    a0.x*=sc; a0.y*=sc; a0.z*=sc; a0.w*=sc;
    a1.x*=sc; a1.y*=sc; a1.z*=sc; a1.w*=sc;
    a2.x*=sc; a2.y*=sc; a2.z*=sc; a2.w*=sc;
    a3.x*=sc; a3.y*=sc; a3.z*=sc; a3.w*=sc;
    *(float4*)(vp + 0)  = a0; *(float4*)(vp + 4)  = a1;
    *(float4*)(vp + 8)  = a2; *(float4*)(vp + 12) = a3;
    if (last) out[idx] = sqrtf(n2 * sc * sc + 1e-9f);
}

// ---------------- launch ----------------
extern "C" void kernel_launch(void* const* d_in, const int* in_sizes, int n_in,
                              void* d_out, int out_size) {
    const int*   word   = (const int*)d_in[0];
    const int*   tag    = (const int*)d_in[1];
    const int*   pos1   = (const int*)d_in[2];
    const int*   pos2   = (const int*)d_in[3];
    const float* we     = (const float*)d_in[4];
    const float* te     = (const float*)d_in[5];
    const float* p1e    = (const float*)d_in[6];
    const float* p2e    = (const float*)d_in[7];
    const float* wihf   = (const float*)d_in[8];
    const float* whhf   = (const float*)d_in[9];
    const float* bihf   = (const float*)d_in[10];
    const float* bhhf   = (const float*)d_in[11];
    const float* wihb   = (const float*)d_in[12];
    const float* whhb   = (const float*)d_in[13];
    const float* bihb   = (const float*)d_in[14];
    const float* bhhb   = (const float*)d_in[15];
    const float* wcaps  = (const float*)d_in[16];
    const float* broute = (const float*)d_in[17];
    float* out = (float*)d_out;

    cudaFuncSetAttribute(lstm_kernel, cudaFuncAttributeMaxDynamicSharedMemorySize, LSTM_SMEM);

    embed_kernel<<<(BB*LL*IND + 255)/256, 256>>>(word, tag, pos1, pos2, we, te, p1e, p2e);

    dim3 gg(16, 200, 2);
    gemm_xg_kernel<<<gg, 256>>>(wihf, wihb, bihf, bhhf, bihb, bhhb);

    lstm_kernel<<<256, 256, LSTM_SMEM>>>(whhf, whhb);

    addx_kernel<<<(BB*LL*HID + 255)/256, 256>>>();
    entity_att_kernel<<<BB, 128>>>(pos1, pos2);
    usq_kernel<<<(BB*NCAP + 255)/256, 256>>>();
    uhat_kernel<<<NCAP, 256>>>(wcaps);

    float *sptr, *vptr;
    cudaGetSymbolAddress((void**)&sptr, g_s);
    cudaGetSymbolAddress((void**)&vptr, g_v);
    cudaMemsetAsync(vptr, 0, BB*ODIM*sizeof(float));
    for (int it = 0; it < 3; ++it) {
        cudaMemsetAsync(sptr, 0, BB*ODIM*sizeof(float));
        route_kernel<<<BB*8, 320>>>(it == 0 ? 1 : 0, broute);
        squash_v_kernel<<<(BB*NCLS + 127)/128, 128>>>(out, it == 2 ? 1 : 0);
    }
    (void)in_sizes; (void)n_in; (void)out_size;
}